// round 1
// baseline (speedup 1.0000x reference)
#include <cuda_runtime.h>
#include <math.h>

#define NB 4
#define NL 2048
#define ND 1024
#define NF 4096
#define NH 16
#define NE 64

// Scratch (device globals; no allocations allowed)
__device__ float g_attn[(size_t)NB * NL * ND];   //  33.5 MB : x + attention out
__device__ float g_ln1 [(size_t)NB * NL * ND];   //  33.5 MB : LN1 output
__device__ float g_hid [(size_t)NB * NL * NF];   // 134.2 MB : FFN hidden
__device__ float g_z   [(size_t)NB * NL * ND];   //  33.5 MB : pre-LN2

// ---------------------------------------------------------------------------
// Flash attention (Q=K=V=x per head) + residual.  BM=BN=64, 256 threads.
// Dynamic smem layout (floats):
//   QsT [64][64]  e-major (QsT[e*64+m])          offset 0
//   KsT [64][64]  e-major (KsT[e*64+n])          offset 4096
//   Vs  [64][64]  n-major (Vs[n*64+e])           offset 8192
//   Ps  [64][68]  row-major, pad 4               offset 12288
//   mrow[64], lrow[64], arow[64]                 offset 16640
// total = 16832 floats = 67328 bytes
// ---------------------------------------------------------------------------
__global__ __launch_bounds__(256) void attn_kernel(const float* __restrict__ x,
                                                   float* __restrict__ out)
{
    extern __shared__ float sm[];
    float* QsT  = sm;
    float* KsT  = sm + 4096;
    float* Vs   = sm + 8192;
    float* Ps   = sm + 12288;
    float* mrow = sm + 16640;
    float* lrow = mrow + 64;
    float* arow = lrow + 64;

    const int tid  = threadIdx.x;
    const int b    = blockIdx.x >> 4;
    const int h    = blockIdx.x & 15;
    const int qblk = blockIdx.y;
    const float* xb = x + (size_t)b * NL * ND + h * NE;

    // Load Q tile, transposed into QsT
#pragma unroll
    for (int it = 0; it < 4; ++it) {
        int idx = tid + it * 256;           // 0..1023
        int m = idx >> 4, c4 = idx & 15;
        float4 v = *(const float4*)(xb + (size_t)(qblk * 64 + m) * ND + c4 * 4);
        int e = c4 * 4;
        QsT[(e + 0) * 64 + m] = v.x;
        QsT[(e + 1) * 64 + m] = v.y;
        QsT[(e + 2) * 64 + m] = v.z;
        QsT[(e + 3) * 64 + m] = v.w;
    }
    if (tid < 64) { mrow[tid] = -1e30f; lrow[tid] = 0.f; }

    const int tx = tid & 15, ty = tid >> 4;
    float o[4][4];
#pragma unroll
    for (int i = 0; i < 4; ++i)
#pragma unroll
        for (int j = 0; j < 4; ++j) o[i][j] = 0.f;

    __syncthreads();

    for (int kb = 0; kb < NL / 64; ++kb) {
        // Load K/V tile once: row-major into Vs, transposed into KsT
#pragma unroll
        for (int it = 0; it < 4; ++it) {
            int idx = tid + it * 256;
            int n = idx >> 4, c4 = idx & 15;
            float4 v = *(const float4*)(xb + (size_t)(kb * 64 + n) * ND + c4 * 4);
            *(float4*)(Vs + n * 64 + c4 * 4) = v;
            int e = c4 * 4;
            KsT[(e + 0) * 64 + n] = v.x;
            KsT[(e + 1) * 64 + n] = v.y;
            KsT[(e + 2) * 64 + n] = v.z;
            KsT[(e + 3) * 64 + n] = v.w;
        }
        __syncthreads();

        // S = Q K^T  (4x4 register tile per thread)
        float s[4][4];
#pragma unroll
        for (int i = 0; i < 4; ++i)
#pragma unroll
            for (int j = 0; j < 4; ++j) s[i][j] = 0.f;

#pragma unroll 8
        for (int k = 0; k < 64; ++k) {
            float4 aq = *(const float4*)(QsT + k * 64 + ty * 4);
            float4 bk = *(const float4*)(KsT + k * 64 + tx * 4);
            float a_[4] = {aq.x, aq.y, aq.z, aq.w};
            float b_[4] = {bk.x, bk.y, bk.z, bk.w};
#pragma unroll
            for (int i = 0; i < 4; ++i)
#pragma unroll
                for (int j = 0; j < 4; ++j) s[i][j] += a_[i] * b_[j];
        }
#pragma unroll
        for (int i = 0; i < 4; ++i)
#pragma unroll
            for (int j = 0; j < 4; ++j)
                Ps[(ty * 4 + i) * 68 + tx * 4 + j] = s[i][j] * 0.125f;
        __syncthreads();

        // Online-softmax row stats: 4 threads per row
        {
            int r = tid >> 2, q = tid & 3;
            float* prow = Ps + r * 68 + q * 16;
            float4 v0 = *(float4*)(prow);
            float4 v1 = *(float4*)(prow + 4);
            float4 v2 = *(float4*)(prow + 8);
            float4 v3 = *(float4*)(prow + 12);
            float mx = fmaxf(fmaxf(fmaxf(v0.x, v0.y), fmaxf(v0.z, v0.w)),
                      fmaxf(fmaxf(fmaxf(v1.x, v1.y), fmaxf(v1.z, v1.w)),
                      fmaxf(fmaxf(fmaxf(v2.x, v2.y), fmaxf(v2.z, v2.w)),
                            fmaxf(fmaxf(v3.x, v3.y), fmaxf(v3.z, v3.w)))));
            mx = fmaxf(mx, __shfl_xor_sync(0xffffffffu, mx, 1));
            mx = fmaxf(mx, __shfl_xor_sync(0xffffffffu, mx, 2));
            float mold = mrow[r];
            float mnew = fmaxf(mold, mx);
            v0.x = __expf(v0.x - mnew); v0.y = __expf(v0.y - mnew);
            v0.z = __expf(v0.z - mnew); v0.w = __expf(v0.w - mnew);
            v1.x = __expf(v1.x - mnew); v1.y = __expf(v1.y - mnew);
            v1.z = __expf(v1.z - mnew); v1.w = __expf(v1.w - mnew);
            v2.x = __expf(v2.x - mnew); v2.y = __expf(v2.y - mnew);
            v2.z = __expf(v2.z - mnew); v2.w = __expf(v2.w - mnew);
            v3.x = __expf(v3.x - mnew); v3.y = __expf(v3.y - mnew);
            v3.z = __expf(v3.z - mnew); v3.w = __expf(v3.w - mnew);
            *(float4*)(prow)      = v0;
            *(float4*)(prow + 4)  = v1;
            *(float4*)(prow + 8)  = v2;
            *(float4*)(prow + 12) = v3;
            float sum = (v0.x + v0.y + v0.z + v0.w) + (v1.x + v1.y + v1.z + v1.w)
                      + (v2.x + v2.y + v2.z + v2.w) + (v3.x + v3.y + v3.z + v3.w);
            sum += __shfl_xor_sync(0xffffffffu, sum, 1);
            sum += __shfl_xor_sync(0xffffffffu, sum, 2);
            if (q == 0) {
                float alpha = __expf(mold - mnew);
                arow[r] = alpha;
                mrow[r] = mnew;
                lrow[r] = lrow[r] * alpha + sum;
            }
        }
        __syncthreads();

        // Rescale O, accumulate O += P V
        float al[4];
#pragma unroll
        for (int i = 0; i < 4; ++i) al[i] = arow[ty * 4 + i];
#pragma unroll
        for (int i = 0; i < 4; ++i)
#pragma unroll
            for (int j = 0; j < 4; ++j) o[i][j] *= al[i];

#pragma unroll 8
        for (int n = 0; n < 64; ++n) {
            float4 bv = *(const float4*)(Vs + n * 64 + tx * 4);
            float b_[4] = {bv.x, bv.y, bv.z, bv.w};
            float a_[4];
#pragma unroll
            for (int i = 0; i < 4; ++i) a_[i] = Ps[(ty * 4 + i) * 68 + n];
#pragma unroll
            for (int i = 0; i < 4; ++i)
#pragma unroll
                for (int j = 0; j < 4; ++j) o[i][j] += a_[i] * b_[j];
        }
        __syncthreads();
    }

    // Epilogue: out = x + O / l   (residual fused)
    float linv[4];
#pragma unroll
    for (int i = 0; i < 4; ++i) linv[i] = 1.f / lrow[ty * 4 + i];
    float* ob = out + (size_t)b * NL * ND + h * NE;
#pragma unroll
    for (int i = 0; i < 4; ++i) {
        int m = qblk * 64 + ty * 4 + i;
#pragma unroll
        for (int j = 0; j < 4; ++j) {
            int e = tx * 4 + j;
            size_t gi = (size_t)m * ND + e;
            ob[gi] = xb[gi] + o[i][j] * linv[i];
        }
    }
}

// ---------------------------------------------------------------------------
// NT GEMM: C[m,n] = sum_k A[m*K+k] * B[n*K+k]  (+ epilogue)
// 128x128 block tile, BK=16, 256 threads, 8x8 per thread (2x2 x 4x4 split).
// do_relu=1: C = relu(acc + bias[n]);  do_relu=0: C = acc + bias[n] + res[m,n]
// ---------------------------------------------------------------------------
__global__ __launch_bounds__(256) void gemm_nt(const float* __restrict__ A,
                                               const float* __restrict__ Bm,
                                               const float* __restrict__ bias,
                                               const float* __restrict__ res,
                                               float* __restrict__ C,
                                               int M, int N, int K, int do_relu)
{
    __shared__ float AsT[16 * 128];
    __shared__ float BsT[16 * 128];
    const int tid = threadIdx.x;
    const int n0 = blockIdx.x * 128;
    const int m0 = blockIdx.y * 128;
    const int tx = tid & 15, ty = tid >> 4;

    float c[8][8];
#pragma unroll
    for (int i = 0; i < 8; ++i)
#pragma unroll
        for (int j = 0; j < 8; ++j) c[i][j] = 0.f;

    for (int k0 = 0; k0 < K; k0 += 16) {
#pragma unroll
        for (int it = 0; it < 2; ++it) {
            int idx = tid + it * 256;       // 0..511
            int r = idx >> 2, kq = (idx & 3) * 4;
            float4 va = *(const float4*)(A + (size_t)(m0 + r) * K + k0 + kq);
            AsT[(kq + 0) * 128 + r] = va.x;
            AsT[(kq + 1) * 128 + r] = va.y;
            AsT[(kq + 2) * 128 + r] = va.z;
            AsT[(kq + 3) * 128 + r] = va.w;
            float4 vb = *(const float4*)(Bm + (size_t)(n0 + r) * K + k0 + kq);
            BsT[(kq + 0) * 128 + r] = vb.x;
            BsT[(kq + 1) * 128 + r] = vb.y;
            BsT[(kq + 2) * 128 + r] = vb.z;
            BsT[(kq + 3) * 128 + r] = vb.w;
        }
        __syncthreads();
#pragma unroll
        for (int k = 0; k < 16; ++k) {
            float a_[8], b_[8];
            *(float4*)(a_)     = *(const float4*)(AsT + k * 128 + ty * 4);
            *(float4*)(a_ + 4) = *(const float4*)(AsT + k * 128 + 64 + ty * 4);
            *(float4*)(b_)     = *(const float4*)(BsT + k * 128 + tx * 4);
            *(float4*)(b_ + 4) = *(const float4*)(BsT + k * 128 + 64 + tx * 4);
#pragma unroll
            for (int i = 0; i < 8; ++i)
#pragma unroll
                for (int j = 0; j < 8; ++j) c[i][j] += a_[i] * b_[j];
        }
        __syncthreads();
    }

#pragma unroll
    for (int ih = 0; ih < 2; ++ih)
#pragma unroll
        for (int il = 0; il < 4; ++il) {
            int m = m0 + ih * 64 + ty * 4 + il;
            int i = ih * 4 + il;
#pragma unroll
            for (int jh = 0; jh < 2; ++jh) {
                int n = n0 + jh * 64 + tx * 4;
                int j = jh * 4;
                float4 bv = *(const float4*)(bias + n);
                float4 v;
                v.x = c[i][j + 0] + bv.x;
                v.y = c[i][j + 1] + bv.y;
                v.z = c[i][j + 2] + bv.z;
                v.w = c[i][j + 3] + bv.w;
                if (do_relu) {
                    v.x = fmaxf(v.x, 0.f); v.y = fmaxf(v.y, 0.f);
                    v.z = fmaxf(v.z, 0.f); v.w = fmaxf(v.w, 0.f);
                } else {
                    float4 rv = *(const float4*)(res + (size_t)m * N + n);
                    v.x += rv.x; v.y += rv.y; v.z += rv.z; v.w += rv.w;
                }
                *(float4*)(C + (size_t)m * N + n) = v;
            }
        }
}

// ---------------------------------------------------------------------------
// LayerNorm over last dim (D=1024). One block per row, 256 threads, float4.
// ---------------------------------------------------------------------------
__global__ __launch_bounds__(256) void ln_kernel(const float* __restrict__ in,
                                                 const float* __restrict__ g,
                                                 const float* __restrict__ be,
                                                 float* __restrict__ out)
{
    __shared__ float sred[8], ssred[8];
    const int row = blockIdx.x;
    const int tid = threadIdx.x;
    const float4 v = *(const float4*)(in + (size_t)row * ND + tid * 4);
    float s  = v.x + v.y + v.z + v.w;
    float ss = v.x * v.x + v.y * v.y + v.z * v.z + v.w * v.w;
#pragma unroll
    for (int o = 16; o; o >>= 1) {
        s  += __shfl_xor_sync(0xffffffffu, s,  o);
        ss += __shfl_xor_sync(0xffffffffu, ss, o);
    }
    if ((tid & 31) == 0) { sred[tid >> 5] = s; ssred[tid >> 5] = ss; }
    __syncthreads();
    s = 0.f; ss = 0.f;
#pragma unroll
    for (int w = 0; w < 8; ++w) { s += sred[w]; ss += ssred[w]; }
    float mean = s * (1.f / ND);
    float var  = ss * (1.f / ND) - mean * mean;
    float rstd = rsqrtf(var + 1e-5f);
    int d = tid * 4;
    float4 gv = *(const float4*)(g + d);
    float4 bv = *(const float4*)(be + d);
    float4 ov;
    ov.x = (v.x - mean) * rstd * gv.x + bv.x;
    ov.y = (v.y - mean) * rstd * gv.y + bv.y;
    ov.z = (v.z - mean) * rstd * gv.z + bv.z;
    ov.w = (v.w - mean) * rstd * gv.w + bv.w;
    *(float4*)(out + (size_t)row * ND + d) = ov;
}

// ---------------------------------------------------------------------------
extern "C" void kernel_launch(void* const* d_in, const int* in_sizes, int n_in,
                              void* d_out, int out_size)
{
    (void)in_sizes; (void)n_in; (void)out_size;
    const float* x   = (const float*)d_in[0];
    const float* w1  = (const float*)d_in[1];
    const float* b1  = (const float*)d_in[2];
    const float* w2  = (const float*)d_in[3];
    const float* b2  = (const float*)d_in[4];
    const float* g1  = (const float*)d_in[5];
    const float* be1 = (const float*)d_in[6];
    const float* g2  = (const float*)d_in[7];
    const float* be2 = (const float*)d_in[8];
    float* out = (float*)d_out;

    float *attn_p, *ln1_p, *hid_p, *z_p;
    cudaGetSymbolAddress((void**)&attn_p, g_attn);
    cudaGetSymbolAddress((void**)&ln1_p,  g_ln1);
    cudaGetSymbolAddress((void**)&hid_p,  g_hid);
    cudaGetSymbolAddress((void**)&z_p,    g_z);

    const int ATTN_SMEM = 16832 * 4;   // 67328 bytes
    cudaFuncSetAttribute(attn_kernel, cudaFuncAttributeMaxDynamicSharedMemorySize, ATTN_SMEM);

    // 1) attention + residual
    attn_kernel<<<dim3(NB * NH, NL / 64), 256, ATTN_SMEM>>>(x, attn_p);
    // 2) LN1
    ln_kernel<<<NB * NL, 256>>>(attn_p, g1, be1, ln1_p);
    // 3) hidden = relu(ln1 @ w1^T + b1)   M=8192 N=4096 K=1024
    gemm_nt<<<dim3(NF / 128, (NB * NL) / 128), 256>>>(ln1_p, w1, b1, nullptr, hid_p,
                                                      NB * NL, NF, ND, 1);
    // 4) z = hidden @ w2^T + b2 + ln1     M=8192 N=1024 K=4096
    gemm_nt<<<dim3(ND / 128, (NB * NL) / 128), 256>>>(hid_p, w2, b2, ln1_p, z_p,
                                                      NB * NL, ND, NF, 0);
    // 5) LN2 -> output
    ln_kernel<<<NB * NL, 256>>>(z_p, g2, be2, out);
}

// round 2
// speedup vs baseline: 1.5896x; 1.5896x over previous
#include <cuda_runtime.h>
#include <math.h>
#include <stdint.h>

#define NB 4
#define NL 2048
#define ND 1024
#define NF 4096
#define NH 16
#define NE 64

// Scratch (device globals; no allocations allowed)
__device__ float g_attn[(size_t)NB * NL * ND];
__device__ float g_ln1 [(size_t)NB * NL * ND];
__device__ float g_hid [(size_t)NB * NL * NF];
__device__ float g_z   [(size_t)NB * NL * ND];

// ---------------------------------------------------------------------------
// Flash attention (Q=K=V=x per head) + residual.  BM=BN=64, 256 threads.
// ---------------------------------------------------------------------------
__global__ __launch_bounds__(256) void attn_kernel(const float* __restrict__ x,
                                                   float* __restrict__ out)
{
    extern __shared__ float sm[];
    float* QsT  = sm;
    float* KsT  = sm + 4096;
    float* Vs   = sm + 8192;
    float* Ps   = sm + 12288;
    float* mrow = sm + 16640;
    float* lrow = mrow + 64;
    float* arow = lrow + 64;

    const int tid  = threadIdx.x;
    const int b    = blockIdx.x >> 4;
    const int h    = blockIdx.x & 15;
    const int qblk = blockIdx.y;
    const float* xb = x + (size_t)b * NL * ND + h * NE;

#pragma unroll
    for (int it = 0; it < 4; ++it) {
        int idx = tid + it * 256;
        int m = idx >> 4, c4 = idx & 15;
        float4 v = *(const float4*)(xb + (size_t)(qblk * 64 + m) * ND + c4 * 4);
        int e = c4 * 4;
        QsT[(e + 0) * 64 + m] = v.x;
        QsT[(e + 1) * 64 + m] = v.y;
        QsT[(e + 2) * 64 + m] = v.z;
        QsT[(e + 3) * 64 + m] = v.w;
    }
    if (tid < 64) { mrow[tid] = -1e30f; lrow[tid] = 0.f; }

    const int tx = tid & 15, ty = tid >> 4;
    float o[4][4];
#pragma unroll
    for (int i = 0; i < 4; ++i)
#pragma unroll
        for (int j = 0; j < 4; ++j) o[i][j] = 0.f;

    __syncthreads();

    for (int kb = 0; kb < NL / 64; ++kb) {
#pragma unroll
        for (int it = 0; it < 4; ++it) {
            int idx = tid + it * 256;
            int n = idx >> 4, c4 = idx & 15;
            float4 v = *(const float4*)(xb + (size_t)(kb * 64 + n) * ND + c4 * 4);
            *(float4*)(Vs + n * 64 + c4 * 4) = v;
            int e = c4 * 4;
            KsT[(e + 0) * 64 + n] = v.x;
            KsT[(e + 1) * 64 + n] = v.y;
            KsT[(e + 2) * 64 + n] = v.z;
            KsT[(e + 3) * 64 + n] = v.w;
        }
        __syncthreads();

        float s[4][4];
#pragma unroll
        for (int i = 0; i < 4; ++i)
#pragma unroll
            for (int j = 0; j < 4; ++j) s[i][j] = 0.f;

#pragma unroll 8
        for (int k = 0; k < 64; ++k) {
            float4 aq = *(const float4*)(QsT + k * 64 + ty * 4);
            float4 bk = *(const float4*)(KsT + k * 64 + tx * 4);
            float a_[4] = {aq.x, aq.y, aq.z, aq.w};
            float b_[4] = {bk.x, bk.y, bk.z, bk.w};
#pragma unroll
            for (int i = 0; i < 4; ++i)
#pragma unroll
                for (int j = 0; j < 4; ++j) s[i][j] += a_[i] * b_[j];
        }
#pragma unroll
        for (int i = 0; i < 4; ++i)
#pragma unroll
            for (int j = 0; j < 4; ++j)
                Ps[(ty * 4 + i) * 68 + tx * 4 + j] = s[i][j] * 0.125f;
        __syncthreads();

        {
            int r = tid >> 2, q = tid & 3;
            float* prow = Ps + r * 68 + q * 16;
            float4 v0 = *(float4*)(prow);
            float4 v1 = *(float4*)(prow + 4);
            float4 v2 = *(float4*)(prow + 8);
            float4 v3 = *(float4*)(prow + 12);
            float mx = fmaxf(fmaxf(fmaxf(v0.x, v0.y), fmaxf(v0.z, v0.w)),
                      fmaxf(fmaxf(fmaxf(v1.x, v1.y), fmaxf(v1.z, v1.w)),
                      fmaxf(fmaxf(fmaxf(v2.x, v2.y), fmaxf(v2.z, v2.w)),
                            fmaxf(fmaxf(v3.x, v3.y), fmaxf(v3.z, v3.w)))));
            mx = fmaxf(mx, __shfl_xor_sync(0xffffffffu, mx, 1));
            mx = fmaxf(mx, __shfl_xor_sync(0xffffffffu, mx, 2));
            float mold = mrow[r];
            float mnew = fmaxf(mold, mx);
            v0.x = __expf(v0.x - mnew); v0.y = __expf(v0.y - mnew);
            v0.z = __expf(v0.z - mnew); v0.w = __expf(v0.w - mnew);
            v1.x = __expf(v1.x - mnew); v1.y = __expf(v1.y - mnew);
            v1.z = __expf(v1.z - mnew); v1.w = __expf(v1.w - mnew);
            v2.x = __expf(v2.x - mnew); v2.y = __expf(v2.y - mnew);
            v2.z = __expf(v2.z - mnew); v2.w = __expf(v2.w - mnew);
            v3.x = __expf(v3.x - mnew); v3.y = __expf(v3.y - mnew);
            v3.z = __expf(v3.z - mnew); v3.w = __expf(v3.w - mnew);
            *(float4*)(prow)      = v0;
            *(float4*)(prow + 4)  = v1;
            *(float4*)(prow + 8)  = v2;
            *(float4*)(prow + 12) = v3;
            float sum = (v0.x + v0.y + v0.z + v0.w) + (v1.x + v1.y + v1.z + v1.w)
                      + (v2.x + v2.y + v2.z + v2.w) + (v3.x + v3.y + v3.z + v3.w);
            sum += __shfl_xor_sync(0xffffffffu, sum, 1);
            sum += __shfl_xor_sync(0xffffffffu, sum, 2);
            if (q == 0) {
                float alpha = __expf(mold - mnew);
                arow[r] = alpha;
                mrow[r] = mnew;
                lrow[r] = lrow[r] * alpha + sum;
            }
        }
        __syncthreads();

        float al[4];
#pragma unroll
        for (int i = 0; i < 4; ++i) al[i] = arow[ty * 4 + i];
#pragma unroll
        for (int i = 0; i < 4; ++i)
#pragma unroll
            for (int j = 0; j < 4; ++j) o[i][j] *= al[i];

#pragma unroll 8
        for (int n = 0; n < 64; ++n) {
            float4 bv = *(const float4*)(Vs + n * 64 + tx * 4);
            float b_[4] = {bv.x, bv.y, bv.z, bv.w};
            float a_[4];
#pragma unroll
            for (int i = 0; i < 4; ++i) a_[i] = Ps[(ty * 4 + i) * 68 + n];
#pragma unroll
            for (int i = 0; i < 4; ++i)
#pragma unroll
                for (int j = 0; j < 4; ++j) o[i][j] += a_[i] * b_[j];
        }
        __syncthreads();
    }

    float linv[4];
#pragma unroll
    for (int i = 0; i < 4; ++i) linv[i] = 1.f / lrow[ty * 4 + i];
    float* ob = out + (size_t)b * NL * ND + h * NE;
#pragma unroll
    for (int i = 0; i < 4; ++i) {
        int m = qblk * 64 + ty * 4 + i;
#pragma unroll
        for (int j = 0; j < 4; ++j) {
            int e = tx * 4 + j;
            size_t gi = (size_t)m * ND + e;
            ob[gi] = xb[gi] + o[i][j] * linv[i];
        }
    }
}

// ---------------------------------------------------------------------------
// TF32 tensor-core NT GEMM: C[m,n] = sum_k A[m,k]*B[n,k]  (+ epilogue)
// 128x128 tile, BK=32, 256 threads = 8 warps (2m x 4n), warp tile 64x32.
// mma.sync.aligned.m16n8k8.row.col.f32.tf32.tf32.f32
// smem stride 36 words: conflict-free for both STS.128 stores and frag loads.
// ---------------------------------------------------------------------------
#define SA 36

__device__ __forceinline__ uint32_t f2tf32(float x) {
    uint32_t r;
    asm("cvt.rna.tf32.f32 %0, %1;" : "=r"(r) : "f"(x));
    return r;
}

__device__ __forceinline__ void mma_tf32(float* d, const uint32_t* a, const uint32_t* b) {
    asm volatile(
        "mma.sync.aligned.m16n8k8.row.col.f32.tf32.tf32.f32 "
        "{%0,%1,%2,%3}, {%4,%5,%6,%7}, {%8,%9}, {%0,%1,%2,%3};"
        : "+f"(d[0]), "+f"(d[1]), "+f"(d[2]), "+f"(d[3])
        : "r"(a[0]), "r"(a[1]), "r"(a[2]), "r"(a[3]), "r"(b[0]), "r"(b[1]));
}

__global__ __launch_bounds__(256, 2) void gemm_tf32(const float* __restrict__ A,
                                                    const float* __restrict__ Bm,
                                                    const float* __restrict__ bias,
                                                    const float* __restrict__ res,
                                                    float* __restrict__ C,
                                                    int M, int N, int K, int do_relu)
{
    __shared__ uint32_t As[128 * SA];
    __shared__ uint32_t Bs[128 * SA];

    const int tid  = threadIdx.x;
    const int lane = tid & 31;
    const int warp = tid >> 5;
    const int wm   = warp >> 2;        // 0..1
    const int wn   = warp & 3;         // 0..3
    const int g    = lane >> 2;        // 0..7
    const int c    = lane & 3;         // 0..3
    const int n0   = blockIdx.x * 128;
    const int m0   = blockIdx.y * 128;

    float acc[4][4][4];
#pragma unroll
    for (int mt = 0; mt < 4; ++mt)
#pragma unroll
        for (int nt = 0; nt < 4; ++nt)
#pragma unroll
            for (int r = 0; r < 4; ++r) acc[mt][nt][r] = 0.f;

    const int ldr  = tid >> 3;          // 0..31 (row within half-tile... )
    const int ldkq = (tid & 7) * 4;     // k quad

    for (int k0 = 0; k0 < K; k0 += 32) {
        // Load 128x32 A and B tiles (float4 -> tf32 -> STS.128)
#pragma unroll
        for (int it = 0; it < 4; ++it) {
            int r = ldr + it * 32;
            float4 va = *(const float4*)(A + (size_t)(m0 + r) * K + k0 + ldkq);
            uint4 ta = { f2tf32(va.x), f2tf32(va.y), f2tf32(va.z), f2tf32(va.w) };
            *(uint4*)&As[r * SA + ldkq] = ta;
            float4 vb = *(const float4*)(Bm + (size_t)(n0 + r) * K + k0 + ldkq);
            uint4 tb = { f2tf32(vb.x), f2tf32(vb.y), f2tf32(vb.z), f2tf32(vb.w) };
            *(uint4*)&Bs[r * SA + ldkq] = tb;
        }
        __syncthreads();

#pragma unroll
        for (int ks = 0; ks < 4; ++ks) {
            uint32_t af[4][4];
#pragma unroll
            for (int mt = 0; mt < 4; ++mt) {
                int m = wm * 64 + mt * 16 + g;
                int base = m * SA + ks * 8 + c;
                af[mt][0] = As[base];
                af[mt][1] = As[base + 8 * SA];
                af[mt][2] = As[base + 4];
                af[mt][3] = As[base + 8 * SA + 4];
            }
            uint32_t bf[4][2];
#pragma unroll
            for (int nt = 0; nt < 4; ++nt) {
                int n = wn * 32 + nt * 8 + g;
                int base = n * SA + ks * 8 + c;
                bf[nt][0] = Bs[base];
                bf[nt][1] = Bs[base + 4];
            }
#pragma unroll
            for (int mt = 0; mt < 4; ++mt)
#pragma unroll
                for (int nt = 0; nt < 4; ++nt)
                    mma_tf32(acc[mt][nt], af[mt], bf[nt]);
        }
        __syncthreads();
    }

    // Epilogue
#pragma unroll
    for (int mt = 0; mt < 4; ++mt) {
#pragma unroll
        for (int i = 0; i < 2; ++i) {
            int m = m0 + wm * 64 + mt * 16 + g + i * 8;
#pragma unroll
            for (int nt = 0; nt < 4; ++nt) {
                int n = n0 + wn * 32 + nt * 8 + c * 2;
                float2 bv = *(const float2*)(bias + n);
                float2 v;
                v.x = acc[mt][nt][i * 2 + 0] + bv.x;
                v.y = acc[mt][nt][i * 2 + 1] + bv.y;
                if (do_relu) {
                    v.x = fmaxf(v.x, 0.f);
                    v.y = fmaxf(v.y, 0.f);
                } else {
                    float2 rv = *(const float2*)(res + (size_t)m * N + n);
                    v.x += rv.x;
                    v.y += rv.y;
                }
                *(float2*)(C + (size_t)m * N + n) = v;
            }
        }
    }
}

// ---------------------------------------------------------------------------
// LayerNorm over last dim (D=1024). One block per row, 256 threads, float4.
// ---------------------------------------------------------------------------
__global__ __launch_bounds__(256) void ln_kernel(const float* __restrict__ in,
                                                 const float* __restrict__ g,
                                                 const float* __restrict__ be,
                                                 float* __restrict__ out)
{
    __shared__ float sred[8], ssred[8];
    const int row = blockIdx.x;
    const int tid = threadIdx.x;
    const float4 v = *(const float4*)(in + (size_t)row * ND + tid * 4);
    float s  = v.x + v.y + v.z + v.w;
    float ss = v.x * v.x + v.y * v.y + v.z * v.z + v.w * v.w;
#pragma unroll
    for (int o = 16; o; o >>= 1) {
        s  += __shfl_xor_sync(0xffffffffu, s,  o);
        ss += __shfl_xor_sync(0xffffffffu, ss, o);
    }
    if ((tid & 31) == 0) { sred[tid >> 5] = s; ssred[tid >> 5] = ss; }
    __syncthreads();
    s = 0.f; ss = 0.f;
#pragma unroll
    for (int w = 0; w < 8; ++w) { s += sred[w]; ss += ssred[w]; }
    float mean = s * (1.f / ND);
    float var  = ss * (1.f / ND) - mean * mean;
    float rstd = rsqrtf(var + 1e-5f);
    int d = tid * 4;
    float4 gv = *(const float4*)(g + d);
    float4 bv = *(const float4*)(be + d);
    float4 ov;
    ov.x = (v.x - mean) * rstd * gv.x + bv.x;
    ov.y = (v.y - mean) * rstd * gv.y + bv.y;
    ov.z = (v.z - mean) * rstd * gv.z + bv.z;
    ov.w = (v.w - mean) * rstd * gv.w + bv.w;
    *(float4*)(out + (size_t)row * ND + d) = ov;
}

// ---------------------------------------------------------------------------
extern "C" void kernel_launch(void* const* d_in, const int* in_sizes, int n_in,
                              void* d_out, int out_size)
{
    (void)in_sizes; (void)n_in; (void)out_size;
    const float* x   = (const float*)d_in[0];
    const float* w1  = (const float*)d_in[1];
    const float* b1  = (const float*)d_in[2];
    const float* w2  = (const float*)d_in[3];
    const float* b2  = (const float*)d_in[4];
    const float* g1  = (const float*)d_in[5];
    const float* be1 = (const float*)d_in[6];
    const float* g2  = (const float*)d_in[7];
    const float* be2 = (const float*)d_in[8];
    float* out = (float*)d_out;

    float *attn_p, *ln1_p, *hid_p, *z_p;
    cudaGetSymbolAddress((void**)&attn_p, g_attn);
    cudaGetSymbolAddress((void**)&ln1_p,  g_ln1);
    cudaGetSymbolAddress((void**)&hid_p,  g_hid);
    cudaGetSymbolAddress((void**)&z_p,    g_z);

    const int ATTN_SMEM = 16832 * 4;
    cudaFuncSetAttribute(attn_kernel, cudaFuncAttributeMaxDynamicSharedMemorySize, ATTN_SMEM);

    // 1) attention + residual
    attn_kernel<<<dim3(NB * NH, NL / 64), 256, ATTN_SMEM>>>(x, attn_p);
    // 2) LN1
    ln_kernel<<<NB * NL, 256>>>(attn_p, g1, be1, ln1_p);
    // 3) hidden = relu(ln1 @ w1^T + b1)   M=8192 N=4096 K=1024
    gemm_tf32<<<dim3(NF / 128, (NB * NL) / 128), 256>>>(ln1_p, w1, b1, nullptr, hid_p,
                                                        NB * NL, NF, ND, 1);
    // 4) z = hidden @ w2^T + b2 + ln1     M=8192 N=1024 K=4096
    gemm_tf32<<<dim3(ND / 128, (NB * NL) / 128), 256>>>(hid_p, w2, b2, ln1_p, z_p,
                                                        NB * NL, ND, NF, 0);
    // 5) LN2 -> output
    ln_kernel<<<NB * NL, 256>>>(z_p, g2, be2, out);
}

// round 3
// speedup vs baseline: 3.1253x; 1.9661x over previous
#include <cuda_runtime.h>
#include <math.h>
#include <stdint.h>

#define NB 4
#define NL 2048
#define ND 1024
#define NF 4096
#define NH 16
#define NE 64

// Scratch (device globals; no allocations allowed)
__device__ float g_attn[(size_t)NB * NL * ND];
__device__ float g_ln1 [(size_t)NB * NL * ND];
__device__ float g_hid [(size_t)NB * NL * NF];
__device__ float g_z   [(size_t)NB * NL * ND];

__device__ __forceinline__ uint32_t f2tf32(float x) {
    uint32_t r;
    asm("cvt.rna.tf32.f32 %0, %1;" : "=r"(r) : "f"(x));
    return r;
}

__device__ __forceinline__ void mma_tf32(float* d, const uint32_t* a, const uint32_t* b) {
    asm volatile(
        "mma.sync.aligned.m16n8k8.row.col.f32.tf32.tf32.f32 "
        "{%0,%1,%2,%3}, {%4,%5,%6,%7}, {%8,%9}, {%0,%1,%2,%3};"
        : "+f"(d[0]), "+f"(d[1]), "+f"(d[2]), "+f"(d[3])
        : "r"(a[0]), "r"(a[1]), "r"(a[2]), "r"(a[3]), "r"(b[0]), "r"(b[1]));
}

// ---------------------------------------------------------------------------
// Tensor-core flash attention (Q=K=V=x per head) + residual.
// BM=128, BN=64, 256 threads = 8 warps; warp w owns rows 16w..16w+15.
// Smem (uint32 words, stride 68): Qs 128x68, Ts 64x68 (K&V), Ps 128x68.
// Softmax entirely in registers (shfl over 4-lane row groups).
// ---------------------------------------------------------------------------
#define AST 68
#define ATT_SMEM_WORDS (128 * AST + 64 * AST + 128 * AST)

__global__ __launch_bounds__(256) void attn_tc(const float* __restrict__ x,
                                               float* __restrict__ out)
{
    extern __shared__ uint32_t smw[];
    uint32_t* Qs = smw;                       // 128*68
    uint32_t* Ts = smw + 128 * AST;           // 64*68
    uint32_t* Ps = smw + 128 * AST + 64 * AST;// 128*68

    const int tid  = threadIdx.x;
    const int warp = tid >> 5;
    const int lane = tid & 31;
    const int g    = lane >> 2;   // 0..7  (row group)
    const int c    = lane & 3;    // 0..3
    const int b    = blockIdx.x >> 4;
    const int h    = blockIdx.x & 15;
    const int qblk = blockIdx.y;
    const float* xb = x + (size_t)b * NL * ND + h * NE;
    float* ob       = out + (size_t)b * NL * ND + h * NE;

    // Load + convert Q tile (128x64)
#pragma unroll
    for (int it = 0; it < 8; ++it) {
        int idx = tid + it * 256;             // 0..2047
        int row = idx >> 4, q4 = idx & 15;
        float4 v = *(const float4*)(xb + (size_t)(qblk * 128 + row) * ND + q4 * 4);
        uint4 t = { f2tf32(v.x), f2tf32(v.y), f2tf32(v.z), f2tf32(v.w) };
        *(uint4*)&Qs[row * AST + q4 * 4] = t;
    }

    float o[8][4];
#pragma unroll
    for (int nt = 0; nt < 8; ++nt)
#pragma unroll
        for (int r = 0; r < 4; ++r) o[nt][r] = 0.f;
    float m0 = -1e30f, m1 = -1e30f, l0 = 0.f, l1 = 0.f;

    __syncthreads();

    for (int kb = 0; kb < NL / 64; ++kb) {
        // Load + convert K/V tile (64x64) — one copy serves both roles
#pragma unroll
        for (int it = 0; it < 4; ++it) {
            int idx = tid + it * 256;         // 0..1023
            int row = idx >> 4, q4 = idx & 15;
            float4 v = *(const float4*)(xb + (size_t)(kb * 64 + row) * ND + q4 * 4);
            uint4 t = { f2tf32(v.x), f2tf32(v.y), f2tf32(v.z), f2tf32(v.w) };
            *(uint4*)&Ts[row * AST + q4 * 4] = t;
        }
        __syncthreads();

        // S = Q K^T  (warp: 16 x 64)
        float s[8][4];
#pragma unroll
        for (int nt = 0; nt < 8; ++nt)
#pragma unroll
            for (int r = 0; r < 4; ++r) s[nt][r] = 0.f;

#pragma unroll
        for (int ks = 0; ks < 8; ++ks) {
            uint32_t a[4];
            int mb = (warp * 16 + g) * AST + ks * 8 + c;
            a[0] = Qs[mb];
            a[1] = Qs[mb + 8 * AST];
            a[2] = Qs[mb + 4];
            a[3] = Qs[mb + 8 * AST + 4];
#pragma unroll
            for (int nt = 0; nt < 8; ++nt) {
                uint32_t bf[2];
                int nb = (nt * 8 + g) * AST + ks * 8 + c;
                bf[0] = Ts[nb];
                bf[1] = Ts[nb + 4];
                mma_tf32(s[nt], a, bf);
            }
        }

        // Register softmax (rows g and g+8 of this warp's stripe)
        const float sc = 0.125f;
        float mx0 = -1e30f, mx1 = -1e30f;
#pragma unroll
        for (int nt = 0; nt < 8; ++nt) {
            s[nt][0] *= sc; s[nt][1] *= sc; s[nt][2] *= sc; s[nt][3] *= sc;
            mx0 = fmaxf(mx0, fmaxf(s[nt][0], s[nt][1]));
            mx1 = fmaxf(mx1, fmaxf(s[nt][2], s[nt][3]));
        }
        mx0 = fmaxf(mx0, __shfl_xor_sync(0xffffffffu, mx0, 1));
        mx0 = fmaxf(mx0, __shfl_xor_sync(0xffffffffu, mx0, 2));
        mx1 = fmaxf(mx1, __shfl_xor_sync(0xffffffffu, mx1, 1));
        mx1 = fmaxf(mx1, __shfl_xor_sync(0xffffffffu, mx1, 2));
        float mn0 = fmaxf(m0, mx0), mn1 = fmaxf(m1, mx1);
        float al0 = __expf(m0 - mn0), al1 = __expf(m1 - mn1);
        m0 = mn0; m1 = mn1;

        float sum0 = 0.f, sum1 = 0.f;
#pragma unroll
        for (int nt = 0; nt < 8; ++nt) {
            s[nt][0] = __expf(s[nt][0] - mn0);
            s[nt][1] = __expf(s[nt][1] - mn0);
            s[nt][2] = __expf(s[nt][2] - mn1);
            s[nt][3] = __expf(s[nt][3] - mn1);
            sum0 += s[nt][0] + s[nt][1];
            sum1 += s[nt][2] + s[nt][3];
        }
        sum0 += __shfl_xor_sync(0xffffffffu, sum0, 1);
        sum0 += __shfl_xor_sync(0xffffffffu, sum0, 2);
        sum1 += __shfl_xor_sync(0xffffffffu, sum1, 1);
        sum1 += __shfl_xor_sync(0xffffffffu, sum1, 2);
        l0 = l0 * al0 + sum0;
        l1 = l1 * al1 + sum1;

        // Rescale O, stash P (own rows only)
#pragma unroll
        for (int nt = 0; nt < 8; ++nt) {
            o[nt][0] *= al0; o[nt][1] *= al0; o[nt][2] *= al1; o[nt][3] *= al1;
            int pb = (warp * 16 + g) * AST + nt * 8 + 2 * c;
            uint2 p01 = { f2tf32(s[nt][0]), f2tf32(s[nt][1]) };
            *(uint2*)&Ps[pb] = p01;
            uint2 p23 = { f2tf32(s[nt][2]), f2tf32(s[nt][3]) };
            *(uint2*)&Ps[pb + 8 * AST] = p23;
        }
        __syncwarp();

        // O += P V   (warp: 16 x 64, K-dim = 64 keys)
#pragma unroll
        for (int ks = 0; ks < 8; ++ks) {
            uint32_t a[4];
            int pb = (warp * 16 + g) * AST + ks * 8 + c;
            a[0] = Ps[pb];
            a[1] = Ps[pb + 8 * AST];
            a[2] = Ps[pb + 4];
            a[3] = Ps[pb + 8 * AST + 4];
#pragma unroll
            for (int nt = 0; nt < 8; ++nt) {
                uint32_t bf[2];
                int vb = (ks * 8 + c) * AST + nt * 8 + g;
                bf[0] = Ts[vb];
                bf[1] = Ts[vb + 4 * AST];
                mma_tf32(o[nt], a, bf);
            }
        }
        __syncthreads();
    }

    // Epilogue: out = x + O / l
    float li0 = 1.f / l0, li1 = 1.f / l1;
    int mglob = qblk * 128 + warp * 16 + g;
    const float* xr0 = xb + (size_t)mglob * ND;
    const float* xr1 = xr0 + (size_t)8 * ND;
    float* or0 = ob + (size_t)mglob * ND;
    float* or1 = or0 + (size_t)8 * ND;
#pragma unroll
    for (int nt = 0; nt < 8; ++nt) {
        int e = nt * 8 + 2 * c;
        float2 xv0 = *(const float2*)(xr0 + e);
        float2 w0;
        w0.x = xv0.x + o[nt][0] * li0;
        w0.y = xv0.y + o[nt][1] * li0;
        *(float2*)(or0 + e) = w0;
        float2 xv1 = *(const float2*)(xr1 + e);
        float2 w1;
        w1.x = xv1.x + o[nt][2] * li1;
        w1.y = xv1.y + o[nt][3] * li1;
        *(float2*)(or1 + e) = w1;
    }
}

// ---------------------------------------------------------------------------
// TF32 tensor-core NT GEMM (unchanged from R2): 128x128 tile, BK=32.
// ---------------------------------------------------------------------------
#define SA 36

__global__ __launch_bounds__(256, 2) void gemm_tf32(const float* __restrict__ A,
                                                    const float* __restrict__ Bm,
                                                    const float* __restrict__ bias,
                                                    const float* __restrict__ res,
                                                    float* __restrict__ C,
                                                    int M, int N, int K, int do_relu)
{
    __shared__ uint32_t As[128 * SA];
    __shared__ uint32_t Bs[128 * SA];

    const int tid  = threadIdx.x;
    const int lane = tid & 31;
    const int warp = tid >> 5;
    const int wm   = warp >> 2;
    const int wn   = warp & 3;
    const int g    = lane >> 2;
    const int c    = lane & 3;
    const int n0   = blockIdx.x * 128;
    const int m0   = blockIdx.y * 128;

    float acc[4][4][4];
#pragma unroll
    for (int mt = 0; mt < 4; ++mt)
#pragma unroll
        for (int nt = 0; nt < 4; ++nt)
#pragma unroll
            for (int r = 0; r < 4; ++r) acc[mt][nt][r] = 0.f;

    const int ldr  = tid >> 3;
    const int ldkq = (tid & 7) * 4;

    for (int k0 = 0; k0 < K; k0 += 32) {
#pragma unroll
        for (int it = 0; it < 4; ++it) {
            int r = ldr + it * 32;
            float4 va = *(const float4*)(A + (size_t)(m0 + r) * K + k0 + ldkq);
            uint4 ta = { f2tf32(va.x), f2tf32(va.y), f2tf32(va.z), f2tf32(va.w) };
            *(uint4*)&As[r * SA + ldkq] = ta;
            float4 vb = *(const float4*)(Bm + (size_t)(n0 + r) * K + k0 + ldkq);
            uint4 tb = { f2tf32(vb.x), f2tf32(vb.y), f2tf32(vb.z), f2tf32(vb.w) };
            *(uint4*)&Bs[r * SA + ldkq] = tb;
        }
        __syncthreads();

#pragma unroll
        for (int ks = 0; ks < 4; ++ks) {
            uint32_t af[4][4];
#pragma unroll
            for (int mt = 0; mt < 4; ++mt) {
                int m = wm * 64 + mt * 16 + g;
                int base = m * SA + ks * 8 + c;
                af[mt][0] = As[base];
                af[mt][1] = As[base + 8 * SA];
                af[mt][2] = As[base + 4];
                af[mt][3] = As[base + 8 * SA + 4];
            }
            uint32_t bf[4][2];
#pragma unroll
            for (int nt = 0; nt < 4; ++nt) {
                int n = wn * 32 + nt * 8 + g;
                int base = n * SA + ks * 8 + c;
                bf[nt][0] = Bs[base];
                bf[nt][1] = Bs[base + 4];
            }
#pragma unroll
            for (int mt = 0; mt < 4; ++mt)
#pragma unroll
                for (int nt = 0; nt < 4; ++nt)
                    mma_tf32(acc[mt][nt], af[mt], bf[nt]);
        }
        __syncthreads();
    }

#pragma unroll
    for (int mt = 0; mt < 4; ++mt) {
#pragma unroll
        for (int i = 0; i < 2; ++i) {
            int m = m0 + wm * 64 + mt * 16 + g + i * 8;
#pragma unroll
            for (int nt = 0; nt < 4; ++nt) {
                int n = n0 + wn * 32 + nt * 8 + c * 2;
                float2 bv = *(const float2*)(bias + n);
                float2 v;
                v.x = acc[mt][nt][i * 2 + 0] + bv.x;
                v.y = acc[mt][nt][i * 2 + 1] + bv.y;
                if (do_relu) {
                    v.x = fmaxf(v.x, 0.f);
                    v.y = fmaxf(v.y, 0.f);
                } else {
                    float2 rv = *(const float2*)(res + (size_t)m * N + n);
                    v.x += rv.x;
                    v.y += rv.y;
                }
                *(float2*)(C + (size_t)m * N + n) = v;
            }
        }
    }
}

// ---------------------------------------------------------------------------
// LayerNorm over last dim (D=1024). One block per row, 256 threads, float4.
// ---------------------------------------------------------------------------
__global__ __launch_bounds__(256) void ln_kernel(const float* __restrict__ in,
                                                 const float* __restrict__ g,
                                                 const float* __restrict__ be,
                                                 float* __restrict__ out)
{
    __shared__ float sred[8], ssred[8];
    const int row = blockIdx.x;
    const int tid = threadIdx.x;
    const float4 v = *(const float4*)(in + (size_t)row * ND + tid * 4);
    float s  = v.x + v.y + v.z + v.w;
    float ss = v.x * v.x + v.y * v.y + v.z * v.z + v.w * v.w;
#pragma unroll
    for (int o = 16; o; o >>= 1) {
        s  += __shfl_xor_sync(0xffffffffu, s,  o);
        ss += __shfl_xor_sync(0xffffffffu, ss, o);
    }
    if ((tid & 31) == 0) { sred[tid >> 5] = s; ssred[tid >> 5] = ss; }
    __syncthreads();
    s = 0.f; ss = 0.f;
#pragma unroll
    for (int w = 0; w < 8; ++w) { s += sred[w]; ss += ssred[w]; }
    float mean = s * (1.f / ND);
    float var  = ss * (1.f / ND) - mean * mean;
    float rstd = rsqrtf(var + 1e-5f);
    int d = tid * 4;
    float4 gv = *(const float4*)(g + d);
    float4 bv = *(const float4*)(be + d);
    float4 ov;
    ov.x = (v.x - mean) * rstd * gv.x + bv.x;
    ov.y = (v.y - mean) * rstd * gv.y + bv.y;
    ov.z = (v.z - mean) * rstd * gv.z + bv.z;
    ov.w = (v.w - mean) * rstd * gv.w + bv.w;
    *(float4*)(out + (size_t)row * ND + d) = ov;
}

// ---------------------------------------------------------------------------
extern "C" void kernel_launch(void* const* d_in, const int* in_sizes, int n_in,
                              void* d_out, int out_size)
{
    (void)in_sizes; (void)n_in; (void)out_size;
    const float* x   = (const float*)d_in[0];
    const float* w1  = (const float*)d_in[1];
    const float* b1  = (const float*)d_in[2];
    const float* w2  = (const float*)d_in[3];
    const float* b2  = (const float*)d_in[4];
    const float* g1  = (const float*)d_in[5];
    const float* be1 = (const float*)d_in[6];
    const float* g2  = (const float*)d_in[7];
    const float* be2 = (const float*)d_in[8];
    float* out = (float*)d_out;

    float *attn_p, *ln1_p, *hid_p, *z_p;
    cudaGetSymbolAddress((void**)&attn_p, g_attn);
    cudaGetSymbolAddress((void**)&ln1_p,  g_ln1);
    cudaGetSymbolAddress((void**)&hid_p,  g_hid);
    cudaGetSymbolAddress((void**)&z_p,    g_z);

    const int ATT_SMEM = ATT_SMEM_WORDS * 4;   // 87040 bytes
    cudaFuncSetAttribute(attn_tc, cudaFuncAttributeMaxDynamicSharedMemorySize, ATT_SMEM);

    // 1) attention + residual
    attn_tc<<<dim3(NB * NH, NL / 128), 256, ATT_SMEM>>>(x, attn_p);
    // 2) LN1
    ln_kernel<<<NB * NL, 256>>>(attn_p, g1, be1, ln1_p);
    // 3) hidden = relu(ln1 @ w1^T + b1)   M=8192 N=4096 K=1024
    gemm_tf32<<<dim3(NF / 128, (NB * NL) / 128), 256>>>(ln1_p, w1, b1, nullptr, hid_p,
                                                        NB * NL, NF, ND, 1);
    // 4) z = hidden @ w2^T + b2 + ln1     M=8192 N=1024 K=4096
    gemm_tf32<<<dim3(ND / 128, (NB * NL) / 128), 256>>>(hid_p, w2, b2, ln1_p, z_p,
                                                        NB * NL, ND, NF, 0);
    // 5) LN2 -> output
    ln_kernel<<<NB * NL, 256>>>(z_p, g2, be2, out);
}

// round 4
// speedup vs baseline: 3.4165x; 1.0932x over previous
#include <cuda_runtime.h>
#include <math.h>
#include <stdint.h>

#define NB 4
#define NL 2048
#define ND 1024
#define NF 4096
#define NH 16
#define NE 64

// Scratch (device globals; no allocations allowed)
__device__ float    g_attn [(size_t)NB * NL * ND];
__device__ float    g_ln1  [(size_t)NB * NL * ND];
__device__ float    g_z    [(size_t)NB * NL * ND];
__device__ uint32_t g_xtf  [(size_t)NB * NL * ND];   // tf32 copy of x
__device__ uint32_t g_ln1tf[(size_t)NB * NL * ND];   // tf32 copy of ln1
__device__ uint32_t g_hidtf[(size_t)NB * NL * NF];   // FFN hidden, tf32
__device__ uint32_t g_w1tf [(size_t)NF * ND];
__device__ uint32_t g_w2tf [(size_t)ND * NF];

__device__ __forceinline__ uint32_t f2tf32(float x) {
    uint32_t r;
    asm("cvt.rna.tf32.f32 %0, %1;" : "=r"(r) : "f"(x));
    return r;
}

__device__ __forceinline__ void mma_tf32(float* d, const uint32_t* a, const uint32_t* b) {
    asm volatile(
        "mma.sync.aligned.m16n8k8.row.col.f32.tf32.tf32.f32 "
        "{%0,%1,%2,%3}, {%4,%5,%6,%7}, {%8,%9}, {%0,%1,%2,%3};"
        : "+f"(d[0]), "+f"(d[1]), "+f"(d[2]), "+f"(d[3])
        : "r"(a[0]), "r"(a[1]), "r"(a[2]), "r"(a[3]), "r"(b[0]), "r"(b[1]));
}

__device__ __forceinline__ void cp_async16(void* smem_dst, const void* gmem_src) {
    uint32_t s = (uint32_t)__cvta_generic_to_shared(smem_dst);
    asm volatile("cp.async.cg.shared.global [%0], [%1], 16;" :: "r"(s), "l"(gmem_src));
}
#define CP_COMMIT() asm volatile("cp.async.commit_group;")
#define CP_WAIT1()  asm volatile("cp.async.wait_group 1;")

// ---------------------------------------------------------------------------
// f32 -> tf32 conversion (grid-stride, float4)
// ---------------------------------------------------------------------------
__global__ __launch_bounds__(256) void cvt_tf32(const float* __restrict__ in,
                                                uint32_t* __restrict__ out, int n4)
{
    int i = blockIdx.x * 256 + threadIdx.x;
    int stride = gridDim.x * 256;
    for (; i < n4; i += stride) {
        float4 v = *(const float4*)(in + (size_t)i * 4);
        uint4 t = { f2tf32(v.x), f2tf32(v.y), f2tf32(v.z), f2tf32(v.w) };
        *(uint4*)(out + (size_t)i * 4) = t;
    }
}

// ---------------------------------------------------------------------------
// Tensor-core flash attention + residual.  BM=128, BN=64, 256 threads.
// Qs/Ps stride-68; T tile double-buffered via cp.async.
// ---------------------------------------------------------------------------
#define AST 68
#define ATT_SMEM_WORDS (128 * AST + 128 * AST + 2 * 64 * AST)

__global__ __launch_bounds__(256) void attn_tc(const uint32_t* __restrict__ xtf,
                                               const float* __restrict__ x,
                                               float* __restrict__ out)
{
    extern __shared__ uint32_t smw[];
    uint32_t* Qs  = smw;                         // 128*68
    uint32_t* Ps  = smw + 128 * AST;             // 128*68
    uint32_t* Tb0 = smw + 256 * AST;             // 64*68
    uint32_t* Tb1 = Tb0 + 64 * AST;

    const int tid  = threadIdx.x;
    const int warp = tid >> 5;
    const int lane = tid & 31;
    const int g    = lane >> 2;
    const int c    = lane & 3;
    const int b    = blockIdx.x >> 4;
    const int h    = blockIdx.x & 15;
    const int qblk = blockIdx.y;
    const uint32_t* xtb = xtf + (size_t)b * NL * ND + h * NE;
    const float*    xb  = x   + (size_t)b * NL * ND + h * NE;
    float*          ob  = out + (size_t)b * NL * ND + h * NE;

    const int lrow = tid >> 4;          // 0..15
    const int lq4  = (tid & 15) * 4;    // 0..60

    // Q tile (128x64) via cp.async
#pragma unroll
    for (int it = 0; it < 8; ++it) {
        int row = lrow + it * 16;
        cp_async16(&Qs[row * AST + lq4], xtb + (size_t)(qblk * 128 + row) * ND + lq4);
    }
    CP_COMMIT();
    // T stage 0
#pragma unroll
    for (int it = 0; it < 4; ++it) {
        int row = lrow + it * 16;
        cp_async16(&Tb0[row * AST + lq4], xtb + (size_t)row * ND + lq4);
    }
    CP_COMMIT();

    float o[8][4];
#pragma unroll
    for (int nt = 0; nt < 8; ++nt)
#pragma unroll
        for (int r = 0; r < 4; ++r) o[nt][r] = 0.f;
    float m0 = -1e30f, m1 = -1e30f, l0 = 0.f, l1 = 0.f;

    for (int kb = 0; kb < NL / 64; ++kb) {
        // prefetch next T tile
        if (kb + 1 < NL / 64) {
            uint32_t* Tn = (kb & 1) ? Tb0 : Tb1;
#pragma unroll
            for (int it = 0; it < 4; ++it) {
                int row = lrow + it * 16;
                cp_async16(&Tn[row * AST + lq4],
                           xtb + (size_t)((kb + 1) * 64 + row) * ND + lq4);
            }
        }
        CP_COMMIT();
        CP_WAIT1();
        __syncthreads();
        const uint32_t* Ts = (kb & 1) ? Tb1 : Tb0;

        // S = Q K^T  (warp: 16 x 64)
        float s[8][4];
#pragma unroll
        for (int nt = 0; nt < 8; ++nt)
#pragma unroll
            for (int r = 0; r < 4; ++r) s[nt][r] = 0.f;

#pragma unroll
        for (int ks = 0; ks < 8; ++ks) {
            uint32_t a[4];
            int mb = (warp * 16 + g) * AST + ks * 8 + c;
            a[0] = Qs[mb];
            a[1] = Qs[mb + 8 * AST];
            a[2] = Qs[mb + 4];
            a[3] = Qs[mb + 8 * AST + 4];
#pragma unroll
            for (int nt = 0; nt < 8; ++nt) {
                uint32_t bf[2];
                int nb = (nt * 8 + g) * AST + ks * 8 + c;
                bf[0] = Ts[nb];
                bf[1] = Ts[nb + 4];
                mma_tf32(s[nt], a, bf);
            }
        }

        // Register softmax
        const float sc = 0.125f;
        float mx0 = -1e30f, mx1 = -1e30f;
#pragma unroll
        for (int nt = 0; nt < 8; ++nt) {
            s[nt][0] *= sc; s[nt][1] *= sc; s[nt][2] *= sc; s[nt][3] *= sc;
            mx0 = fmaxf(mx0, fmaxf(s[nt][0], s[nt][1]));
            mx1 = fmaxf(mx1, fmaxf(s[nt][2], s[nt][3]));
        }
        mx0 = fmaxf(mx0, __shfl_xor_sync(0xffffffffu, mx0, 1));
        mx0 = fmaxf(mx0, __shfl_xor_sync(0xffffffffu, mx0, 2));
        mx1 = fmaxf(mx1, __shfl_xor_sync(0xffffffffu, mx1, 1));
        mx1 = fmaxf(mx1, __shfl_xor_sync(0xffffffffu, mx1, 2));
        float mn0 = fmaxf(m0, mx0), mn1 = fmaxf(m1, mx1);
        float al0 = __expf(m0 - mn0), al1 = __expf(m1 - mn1);
        m0 = mn0; m1 = mn1;

        float sum0 = 0.f, sum1 = 0.f;
#pragma unroll
        for (int nt = 0; nt < 8; ++nt) {
            s[nt][0] = __expf(s[nt][0] - mn0);
            s[nt][1] = __expf(s[nt][1] - mn0);
            s[nt][2] = __expf(s[nt][2] - mn1);
            s[nt][3] = __expf(s[nt][3] - mn1);
            sum0 += s[nt][0] + s[nt][1];
            sum1 += s[nt][2] + s[nt][3];
        }
        sum0 += __shfl_xor_sync(0xffffffffu, sum0, 1);
        sum0 += __shfl_xor_sync(0xffffffffu, sum0, 2);
        sum1 += __shfl_xor_sync(0xffffffffu, sum1, 1);
        sum1 += __shfl_xor_sync(0xffffffffu, sum1, 2);
        l0 = l0 * al0 + sum0;
        l1 = l1 * al1 + sum1;

        // Rescale O, stash P (own rows only)
#pragma unroll
        for (int nt = 0; nt < 8; ++nt) {
            o[nt][0] *= al0; o[nt][1] *= al0; o[nt][2] *= al1; o[nt][3] *= al1;
            int pb = (warp * 16 + g) * AST + nt * 8 + 2 * c;
            uint2 p01 = { f2tf32(s[nt][0]), f2tf32(s[nt][1]) };
            *(uint2*)&Ps[pb] = p01;
            uint2 p23 = { f2tf32(s[nt][2]), f2tf32(s[nt][3]) };
            *(uint2*)&Ps[pb + 8 * AST] = p23;
        }
        __syncwarp();

        // O += P V
#pragma unroll
        for (int ks = 0; ks < 8; ++ks) {
            uint32_t a[4];
            int pb = (warp * 16 + g) * AST + ks * 8 + c;
            a[0] = Ps[pb];
            a[1] = Ps[pb + 8 * AST];
            a[2] = Ps[pb + 4];
            a[3] = Ps[pb + 8 * AST + 4];
#pragma unroll
            for (int nt = 0; nt < 8; ++nt) {
                uint32_t bf[2];
                int vb = (ks * 8 + c) * AST + nt * 8 + g;
                bf[0] = Ts[vb];
                bf[1] = Ts[vb + 4 * AST];
                mma_tf32(o[nt], a, bf);
            }
        }
        __syncthreads();
    }

    // Epilogue: out = x + O / l
    float li0 = 1.f / l0, li1 = 1.f / l1;
    int mglob = qblk * 128 + warp * 16 + g;
    const float* xr0 = xb + (size_t)mglob * ND;
    const float* xr1 = xr0 + (size_t)8 * ND;
    float* or0 = ob + (size_t)mglob * ND;
    float* or1 = or0 + (size_t)8 * ND;
#pragma unroll
    for (int nt = 0; nt < 8; ++nt) {
        int e = nt * 8 + 2 * c;
        float2 xv0 = *(const float2*)(xr0 + e);
        float2 w0;
        w0.x = xv0.x + o[nt][0] * li0;
        w0.y = xv0.y + o[nt][1] * li0;
        *(float2*)(or0 + e) = w0;
        float2 xv1 = *(const float2*)(xr1 + e);
        float2 w1;
        w1.x = xv1.x + o[nt][2] * li1;
        w1.y = xv1.y + o[nt][3] * li1;
        *(float2*)(or1 + e) = w1;
    }
}

// ---------------------------------------------------------------------------
// TF32 tensor-core NT GEMM, cp.async 2-stage pipeline.
// Inputs pre-converted to tf32 (uint32). 128x128 tile, BK=32, 8 warps.
// mode 1: out_tf = tf32(relu(acc + bias))
// mode 0: out_f  = acc + bias + res
// ---------------------------------------------------------------------------
#define SA 36
#define GST (128 * SA)            // words per matrix per stage
#define GEMM_SMEM_WORDS (4 * GST) // 2 stages x (A + B)

__global__ __launch_bounds__(256, 2) void gemm_tf32p(const uint32_t* __restrict__ A,
                                                     const uint32_t* __restrict__ Bm,
                                                     const float* __restrict__ bias,
                                                     const float* __restrict__ res,
                                                     float* __restrict__ Cf,
                                                     uint32_t* __restrict__ Ct,
                                                     int M, int N, int K, int mode)
{
    extern __shared__ uint32_t dyn[];

    const int tid  = threadIdx.x;
    const int lane = tid & 31;
    const int warp = tid >> 5;
    const int wm   = warp >> 2;
    const int wn   = warp & 3;
    const int g    = lane >> 2;
    const int c    = lane & 3;
    const int n0   = blockIdx.x * 128;
    const int m0   = blockIdx.y * 128;

    const int ldr  = tid >> 3;          // 0..31
    const int ldkq = (tid & 7) * 4;     // 0,4,..,28

    float acc[4][4][4];
#pragma unroll
    for (int mt = 0; mt < 4; ++mt)
#pragma unroll
        for (int nt = 0; nt < 4; ++nt)
#pragma unroll
            for (int r = 0; r < 4; ++r) acc[mt][nt][r] = 0.f;

    // prologue: stage 0
    {
        uint32_t* As = dyn;
        uint32_t* Bs = dyn + GST;
#pragma unroll
        for (int it = 0; it < 4; ++it) {
            int r = ldr + it * 32;
            cp_async16(&As[r * SA + ldkq], A  + (size_t)(m0 + r) * K + ldkq);
            cp_async16(&Bs[r * SA + ldkq], Bm + (size_t)(n0 + r) * K + ldkq);
        }
    }
    CP_COMMIT();

    const int nk = K / 32;
    for (int kt = 0; kt < nk; ++kt) {
        int cur = kt & 1;
        if (kt + 1 < nk) {
            uint32_t* As = dyn + (cur ^ 1) * 2 * GST;
            uint32_t* Bs = As + GST;
            int k0 = (kt + 1) * 32;
#pragma unroll
            for (int it = 0; it < 4; ++it) {
                int r = ldr + it * 32;
                cp_async16(&As[r * SA + ldkq], A  + (size_t)(m0 + r) * K + k0 + ldkq);
                cp_async16(&Bs[r * SA + ldkq], Bm + (size_t)(n0 + r) * K + k0 + ldkq);
            }
        }
        CP_COMMIT();
        CP_WAIT1();
        __syncthreads();

        const uint32_t* As = dyn + cur * 2 * GST;
        const uint32_t* Bs = As + GST;
#pragma unroll
        for (int ks = 0; ks < 4; ++ks) {
            uint32_t af[4][4];
#pragma unroll
            for (int mt = 0; mt < 4; ++mt) {
                int m = wm * 64 + mt * 16 + g;
                int base = m * SA + ks * 8 + c;
                af[mt][0] = As[base];
                af[mt][1] = As[base + 8 * SA];
                af[mt][2] = As[base + 4];
                af[mt][3] = As[base + 8 * SA + 4];
            }
            uint32_t bf[4][2];
#pragma unroll
            for (int nt = 0; nt < 4; ++nt) {
                int n = wn * 32 + nt * 8 + g;
                int base = n * SA + ks * 8 + c;
                bf[nt][0] = Bs[base];
                bf[nt][1] = Bs[base + 4];
            }
#pragma unroll
            for (int mt = 0; mt < 4; ++mt)
#pragma unroll
                for (int nt = 0; nt < 4; ++nt)
                    mma_tf32(acc[mt][nt], af[mt], bf[nt]);
        }
        __syncthreads();
    }

    // Epilogue
#pragma unroll
    for (int mt = 0; mt < 4; ++mt) {
#pragma unroll
        for (int i = 0; i < 2; ++i) {
            int m = m0 + wm * 64 + mt * 16 + g + i * 8;
#pragma unroll
            for (int nt = 0; nt < 4; ++nt) {
                int n = n0 + wn * 32 + nt * 8 + c * 2;
                float2 bv = *(const float2*)(bias + n);
                float vx = acc[mt][nt][i * 2 + 0] + bv.x;
                float vy = acc[mt][nt][i * 2 + 1] + bv.y;
                if (mode) {
                    vx = fmaxf(vx, 0.f);
                    vy = fmaxf(vy, 0.f);
                    uint2 t = { f2tf32(vx), f2tf32(vy) };
                    *(uint2*)(Ct + (size_t)m * N + n) = t;
                } else {
                    float2 rv = *(const float2*)(res + (size_t)m * N + n);
                    float2 v = { vx + rv.x, vy + rv.y };
                    *(float2*)(Cf + (size_t)m * N + n) = v;
                }
            }
        }
    }
}

// ---------------------------------------------------------------------------
// LayerNorm over last dim (D=1024). Optionally writes a tf32 copy.
// ---------------------------------------------------------------------------
__global__ __launch_bounds__(256) void ln_kernel(const float* __restrict__ in,
                                                 const float* __restrict__ g,
                                                 const float* __restrict__ be,
                                                 float* __restrict__ out,
                                                 uint32_t* __restrict__ out_tf)
{
    __shared__ float sred[8], ssred[8];
    const int row = blockIdx.x;
    const int tid = threadIdx.x;
    const float4 v = *(const float4*)(in + (size_t)row * ND + tid * 4);
    float s  = v.x + v.y + v.z + v.w;
    float ss = v.x * v.x + v.y * v.y + v.z * v.z + v.w * v.w;
#pragma unroll
    for (int o = 16; o; o >>= 1) {
        s  += __shfl_xor_sync(0xffffffffu, s,  o);
        ss += __shfl_xor_sync(0xffffffffu, ss, o);
    }
    if ((tid & 31) == 0) { sred[tid >> 5] = s; ssred[tid >> 5] = ss; }
    __syncthreads();
    s = 0.f; ss = 0.f;
#pragma unroll
    for (int w = 0; w < 8; ++w) { s += sred[w]; ss += ssred[w]; }
    float mean = s * (1.f / ND);
    float var  = ss * (1.f / ND) - mean * mean;
    float rstd = rsqrtf(var + 1e-5f);
    int d = tid * 4;
    float4 gv = *(const float4*)(g + d);
    float4 bv = *(const float4*)(be + d);
    float4 ov;
    ov.x = (v.x - mean) * rstd * gv.x + bv.x;
    ov.y = (v.y - mean) * rstd * gv.y + bv.y;
    ov.z = (v.z - mean) * rstd * gv.z + bv.z;
    ov.w = (v.w - mean) * rstd * gv.w + bv.w;
    *(float4*)(out + (size_t)row * ND + d) = ov;
    if (out_tf) {
        uint4 t = { f2tf32(ov.x), f2tf32(ov.y), f2tf32(ov.z), f2tf32(ov.w) };
        *(uint4*)(out_tf + (size_t)row * ND + d) = t;
    }
}

// ---------------------------------------------------------------------------
extern "C" void kernel_launch(void* const* d_in, const int* in_sizes, int n_in,
                              void* d_out, int out_size)
{
    (void)in_sizes; (void)n_in; (void)out_size;
    const float* x   = (const float*)d_in[0];
    const float* w1  = (const float*)d_in[1];
    const float* b1  = (const float*)d_in[2];
    const float* w2  = (const float*)d_in[3];
    const float* b2  = (const float*)d_in[4];
    const float* g1  = (const float*)d_in[5];
    const float* be1 = (const float*)d_in[6];
    const float* g2  = (const float*)d_in[7];
    const float* be2 = (const float*)d_in[8];
    float* out = (float*)d_out;

    float *attn_p, *ln1_p, *z_p;
    uint32_t *xtf_p, *ln1tf_p, *hidtf_p, *w1tf_p, *w2tf_p;
    cudaGetSymbolAddress((void**)&attn_p,  g_attn);
    cudaGetSymbolAddress((void**)&ln1_p,   g_ln1);
    cudaGetSymbolAddress((void**)&z_p,     g_z);
    cudaGetSymbolAddress((void**)&xtf_p,   g_xtf);
    cudaGetSymbolAddress((void**)&ln1tf_p, g_ln1tf);
    cudaGetSymbolAddress((void**)&hidtf_p, g_hidtf);
    cudaGetSymbolAddress((void**)&w1tf_p,  g_w1tf);
    cudaGetSymbolAddress((void**)&w2tf_p,  g_w2tf);

    const int ATT_SMEM  = ATT_SMEM_WORDS * 4;    // 104448 B
    const int GEMM_SMEM = GEMM_SMEM_WORDS * 4;   // 73728 B
    cudaFuncSetAttribute(attn_tc,    cudaFuncAttributeMaxDynamicSharedMemorySize, ATT_SMEM);
    cudaFuncSetAttribute(gemm_tf32p, cudaFuncAttributeMaxDynamicSharedMemorySize, GEMM_SMEM);

    // 0) pre-convert x, w1, w2 to tf32
    cvt_tf32<<<1184, 256>>>(x,  xtf_p,  NB * NL * ND / 4);
    cvt_tf32<<<1184, 256>>>(w1, w1tf_p, NF * ND / 4);
    cvt_tf32<<<1184, 256>>>(w2, w2tf_p, ND * NF / 4);
    // 1) attention + residual
    attn_tc<<<dim3(NB * NH, NL / 128), 256, ATT_SMEM>>>(xtf_p, x, attn_p);
    // 2) LN1 (f32 + tf32 copies)
    ln_kernel<<<NB * NL, 256>>>(attn_p, g1, be1, ln1_p, ln1tf_p);
    // 3) hidden = tf32(relu(ln1 @ w1^T + b1))   M=8192 N=4096 K=1024
    gemm_tf32p<<<dim3(NF / 128, (NB * NL) / 128), 256, GEMM_SMEM>>>(
        ln1tf_p, w1tf_p, b1, nullptr, nullptr, hidtf_p, NB * NL, NF, ND, 1);
    // 4) z = hidden @ w2^T + b2 + ln1           M=8192 N=1024 K=4096
    gemm_tf32p<<<dim3(ND / 128, (NB * NL) / 128), 256, GEMM_SMEM>>>(
        hidtf_p, w2tf_p, b2, ln1_p, z_p, nullptr, NB * NL, ND, NF, 0);
    // 5) LN2 -> output
    ln_kernel<<<NB * NL, 256>>>(z_p, g2, be2, out, nullptr);
}

// round 5
// speedup vs baseline: 3.6118x; 1.0572x over previous
#include <cuda_runtime.h>
#include <math.h>
#include <stdint.h>

#define NB 4
#define NL 2048
#define ND 1024
#define NF 4096
#define NH 16
#define NE 64

// Scratch (device globals; no allocations allowed)
__device__ float    g_attn [(size_t)NB * NL * ND];
__device__ float    g_ln1  [(size_t)NB * NL * ND];
__device__ float    g_z    [(size_t)NB * NL * ND];
__device__ uint32_t g_xtf  [(size_t)NB * NL * ND];   // tf32 x, e-interleaved
__device__ uint32_t g_xT   [(size_t)NB * NH * NE * NL]; // tf32 x^T per (b,h), key-interleaved
__device__ uint32_t g_ln1tf[(size_t)NB * NL * ND];   // tf32 ln1, D-interleaved
__device__ uint32_t g_hidtf[(size_t)NB * NL * NF];   // tf32 hidden, F-interleaved
__device__ uint32_t g_w1tf [(size_t)NF * ND];        // D-interleaved
__device__ uint32_t g_w2tf [(size_t)ND * NF];        // F-interleaved

__device__ __forceinline__ uint32_t f2tf32(float x) {
    uint32_t r;
    asm("cvt.rna.tf32.f32 %0, %1;" : "=r"(r) : "f"(x));
    return r;
}

__device__ __forceinline__ void mma_tf32(float* d, const uint32_t* a, const uint32_t* b) {
    asm volatile(
        "mma.sync.aligned.m16n8k8.row.col.f32.tf32.tf32.f32 "
        "{%0,%1,%2,%3}, {%4,%5,%6,%7}, {%8,%9}, {%0,%1,%2,%3};"
        : "+f"(d[0]), "+f"(d[1]), "+f"(d[2]), "+f"(d[3])
        : "r"(a[0]), "r"(a[1]), "r"(a[2]), "r"(a[3]), "r"(b[0]), "r"(b[1]));
}

__device__ __forceinline__ void cp_async16(void* smem_dst, const void* gmem_src) {
    uint32_t s = (uint32_t)__cvta_generic_to_shared(smem_dst);
    asm volatile("cp.async.cg.shared.global [%0], [%1], 16;" :: "r"(s), "l"(gmem_src));
}
#define CP_COMMIT() asm volatile("cp.async.commit_group;")
#define CP_WAIT1()  asm volatile("cp.async.wait_group 1;")

// ---------------------------------------------------------------------------
// f32 -> tf32, interleaving k within 8-groups: k -> 2*(k&3) + ((k>>2)&1)
// ---------------------------------------------------------------------------
__global__ __launch_bounds__(256) void cvt_il(const float* __restrict__ in,
                                              uint32_t* __restrict__ out, int n4)
{
    int i = blockIdx.x * 256 + threadIdx.x;
    int stride = gridDim.x * 256;
    for (; i < n4; i += stride) {
        float4 v = *(const float4*)(in + (size_t)i * 4);
        size_t d = (size_t)i * 4;
        size_t base = d & ~(size_t)7;
        int off = (d & 4) ? 1 : 0;
        out[base + off + 0] = f2tf32(v.x);
        out[base + off + 2] = f2tf32(v.y);
        out[base + off + 4] = f2tf32(v.z);
        out[base + off + 6] = f2tf32(v.w);
    }
}

// ---------------------------------------------------------------------------
// Build g_xT[b][h][e][l'] = tf32(x[b][l][h*64+e]); l' key-interleaved.
// Block: 256 threads, handles 128 l-rows for one (b,h).
// ---------------------------------------------------------------------------
__global__ __launch_bounds__(256) void transpose_xT(const float* __restrict__ x,
                                                    uint32_t* __restrict__ xT)
{
    __shared__ float tile[128][65];
    const int bh = blockIdx.x;
    const int b  = bh >> 4, h = bh & 15;
    const int l0 = blockIdx.y * 128;
    const float* src = x + ((size_t)b * NL + l0) * ND + h * 64;

#pragma unroll
    for (int it = 0; it < 8; ++it) {
        int idx = threadIdx.x + it * 256;       // 0..2047 float4s
        int row = idx >> 4, c4 = (idx & 15) * 4;
        float4 v = *(const float4*)(src + (size_t)row * ND + c4);
        tile[row][c4 + 0] = v.x;
        tile[row][c4 + 1] = v.y;
        tile[row][c4 + 2] = v.z;
        tile[row][c4 + 3] = v.w;
    }
    __syncthreads();

    uint32_t* dst = xT + (size_t)bh * NE * NL + l0;
#pragma unroll
    for (int it = 0; it < 8; ++it) {
        int idx = threadIdx.x + it * 256;       // 0..2047 uint4s
        int e = idx >> 5, lq = (idx & 31) * 4;
        uint4 t;
        {
            int pp = lq + 0; int l = (pp & ~7) + ((pp & 7) >> 1) + ((pp & 1) << 2);
            t.x = f2tf32(tile[l][e]);
        }
        {
            int pp = lq + 1; int l = (pp & ~7) + ((pp & 7) >> 1) + ((pp & 1) << 2);
            t.y = f2tf32(tile[l][e]);
        }
        {
            int pp = lq + 2; int l = (pp & ~7) + ((pp & 7) >> 1) + ((pp & 1) << 2);
            t.z = f2tf32(tile[l][e]);
        }
        {
            int pp = lq + 3; int l = (pp & ~7) + ((pp & 7) >> 1) + ((pp & 1) << 2);
            t.w = f2tf32(tile[l][e]);
        }
        *(uint4*)(dst + (size_t)e * NL + lq) = t;
    }
}

// ---------------------------------------------------------------------------
// Tensor-core flash attention + residual. BM=128, BN=64, 256 threads, 8 warps.
// Q fragments hoisted to registers; K (Ts) and V (Vs, e-major) tiles
// double-buffered via cp.async; all B-fragments are LDS.64 (interleaved k).
// Smem: Ps 128x72, Ts 2x64x72, Vs 2x64x72 = 27648 words = 110592 B.
// ---------------------------------------------------------------------------
#define AST 72
#define ATT_SMEM_WORDS (128 * AST + 4 * 64 * AST)

__global__ __launch_bounds__(256) void attn_tc(const uint32_t* __restrict__ xtf,
                                               const uint32_t* __restrict__ xT,
                                               const float* __restrict__ x,
                                               float* __restrict__ out)
{
    extern __shared__ uint32_t smw[];
    uint32_t* Ps  = smw;
    uint32_t* Tb0 = smw + 128 * AST;
    uint32_t* Tb1 = Tb0 + 64 * AST;
    uint32_t* Vb0 = Tb1 + 64 * AST;
    uint32_t* Vb1 = Vb0 + 64 * AST;

    const int tid  = threadIdx.x;
    const int warp = tid >> 5;
    const int lane = tid & 31;
    const int g    = lane >> 2;
    const int c    = lane & 3;
    const int b    = blockIdx.x >> 4;
    const int h    = blockIdx.x & 15;
    const int qblk = blockIdx.y;
    const uint32_t* xtb = xtf + (size_t)b * NL * ND + h * NE;
    const uint32_t* xTb = xT + (size_t)(b * NH + h) * NE * NL;
    const float*    xb  = x   + (size_t)b * NL * ND + h * NE;
    float*          ob  = out + (size_t)b * NL * ND + h * NE;

    const int crow = tid >> 2;          // 0..63
    const int coff = (tid & 3) * 4;     // 0..12

    // stage 0: K tile (row-major keys) + V tile (e-major, key-interleaved)
    {
        const uint32_t* srcT = xtb;
        const uint32_t* srcV = xTb;
#pragma unroll
        for (int it = 0; it < 4; ++it) {
            cp_async16(&Tb0[crow * AST + coff + it * 16], srcT + (size_t)crow * ND + coff + it * 16);
            cp_async16(&Vb0[crow * AST + coff + it * 16], srcV + (size_t)crow * NL + coff + it * 16);
        }
    }
    CP_COMMIT();

    // Q fragments (hoisted, from interleaved global)
    uint32_t qf[8][4];
    {
        const uint32_t* q0 = xtb + (size_t)(qblk * 128 + warp * 16 + g) * ND;
        const uint32_t* q8 = q0 + (size_t)8 * ND;
#pragma unroll
        for (int ks = 0; ks < 8; ++ks) {
            uint2 u0 = *(const uint2*)(q0 + ks * 8 + 2 * c);
            uint2 u1 = *(const uint2*)(q8 + ks * 8 + 2 * c);
            qf[ks][0] = u0.x; qf[ks][1] = u1.x; qf[ks][2] = u0.y; qf[ks][3] = u1.y;
        }
    }

    float o[8][4];
#pragma unroll
    for (int nt = 0; nt < 8; ++nt)
#pragma unroll
        for (int r = 0; r < 4; ++r) o[nt][r] = 0.f;
    float m0 = -1e30f, m1 = -1e30f, l0 = 0.f, l1 = 0.f;

    const int sw    = (g & 4) ? 4 : 0;     // Ps column swizzle
    const int prow0 = (warp * 16 + g) * AST;

    for (int kb = 0; kb < NL / 64; ++kb) {
        if (kb + 1 < NL / 64) {
            uint32_t* Tn = (kb & 1) ? Tb0 : Tb1;
            uint32_t* Vn = (kb & 1) ? Vb0 : Vb1;
            const uint32_t* srcT = xtb + (size_t)(kb + 1) * 64 * ND;
            const uint32_t* srcV = xTb + (kb + 1) * 64;
#pragma unroll
            for (int it = 0; it < 4; ++it) {
                cp_async16(&Tn[crow * AST + coff + it * 16], srcT + (size_t)crow * ND + coff + it * 16);
                cp_async16(&Vn[crow * AST + coff + it * 16], srcV + (size_t)crow * NL + coff + it * 16);
            }
        }
        CP_COMMIT();
        CP_WAIT1();
        __syncthreads();
        const uint32_t* Ts = (kb & 1) ? Tb1 : Tb0;
        const uint32_t* Vs = (kb & 1) ? Vb1 : Vb0;

        // S = Q K^T (warp: 16 x 64); B-frags LDS.64
        float s[8][4];
#pragma unroll
        for (int nt = 0; nt < 8; ++nt)
#pragma unroll
            for (int r = 0; r < 4; ++r) s[nt][r] = 0.f;

#pragma unroll
        for (int ks = 0; ks < 8; ++ks) {
#pragma unroll
            for (int nt = 0; nt < 8; ++nt) {
                uint2 bv = *(const uint2*)&Ts[(nt * 8 + g) * AST + ks * 8 + 2 * c];
                uint32_t bf[2] = { bv.x, bv.y };
                mma_tf32(s[nt], qf[ks], bf);
            }
        }

        // Register softmax
        const float sc = 0.125f;
        float mx0 = -1e30f, mx1 = -1e30f;
#pragma unroll
        for (int nt = 0; nt < 8; ++nt) {
            s[nt][0] *= sc; s[nt][1] *= sc; s[nt][2] *= sc; s[nt][3] *= sc;
            mx0 = fmaxf(mx0, fmaxf(s[nt][0], s[nt][1]));
            mx1 = fmaxf(mx1, fmaxf(s[nt][2], s[nt][3]));
        }
        mx0 = fmaxf(mx0, __shfl_xor_sync(0xffffffffu, mx0, 1));
        mx0 = fmaxf(mx0, __shfl_xor_sync(0xffffffffu, mx0, 2));
        mx1 = fmaxf(mx1, __shfl_xor_sync(0xffffffffu, mx1, 1));
        mx1 = fmaxf(mx1, __shfl_xor_sync(0xffffffffu, mx1, 2));
        float mn0 = fmaxf(m0, mx0), mn1 = fmaxf(m1, mx1);
        float al0 = __expf(m0 - mn0), al1 = __expf(m1 - mn1);
        m0 = mn0; m1 = mn1;

        float sum0 = 0.f, sum1 = 0.f;
#pragma unroll
        for (int nt = 0; nt < 8; ++nt) {
            s[nt][0] = __expf(s[nt][0] - mn0);
            s[nt][1] = __expf(s[nt][1] - mn0);
            s[nt][2] = __expf(s[nt][2] - mn1);
            s[nt][3] = __expf(s[nt][3] - mn1);
            sum0 += s[nt][0] + s[nt][1];
            sum1 += s[nt][2] + s[nt][3];
        }
        sum0 += __shfl_xor_sync(0xffffffffu, sum0, 1);
        sum0 += __shfl_xor_sync(0xffffffffu, sum0, 2);
        sum1 += __shfl_xor_sync(0xffffffffu, sum1, 1);
        sum1 += __shfl_xor_sync(0xffffffffu, sum1, 2);
        l0 = l0 * al0 + sum0;
        l1 = l1 * al1 + sum1;

        // Rescale O, stash P (swizzled columns, own rows only)
#pragma unroll
        for (int nt = 0; nt < 8; ++nt) {
            o[nt][0] *= al0; o[nt][1] *= al0; o[nt][2] *= al1; o[nt][3] *= al1;
            int col0 = nt * 8 + ((2 * c) ^ sw);
            uint2 p01 = { f2tf32(s[nt][0]), f2tf32(s[nt][1]) };
            *(uint2*)&Ps[prow0 + col0] = p01;
            uint2 p23 = { f2tf32(s[nt][2]), f2tf32(s[nt][3]) };
            *(uint2*)&Ps[prow0 + 8 * AST + col0] = p23;
        }
        __syncwarp();

        // O += P V ; V B-frags LDS.64 from e-major interleaved tile
#pragma unroll
        for (int ks = 0; ks < 8; ++ks) {
            uint32_t a[4];
            int k0 = ks * 8 + (c ^ sw);
            int k1 = ks * 8 + (c ^ sw ^ 4);
            a[0] = Ps[prow0 + k0];
            a[1] = Ps[prow0 + 8 * AST + k0];
            a[2] = Ps[prow0 + k1];
            a[3] = Ps[prow0 + 8 * AST + k1];
#pragma unroll
            for (int nt = 0; nt < 8; ++nt) {
                uint2 bv = *(const uint2*)&Vs[(nt * 8 + g) * AST + ks * 8 + 2 * c];
                uint32_t bf[2] = { bv.x, bv.y };
                mma_tf32(o[nt], a, bf);
            }
        }
        __syncthreads();
    }

    // Epilogue: out = x + O / l
    float li0 = 1.f / l0, li1 = 1.f / l1;
    int mglob = qblk * 128 + warp * 16 + g;
    const float* xr0 = xb + (size_t)mglob * ND;
    const float* xr1 = xr0 + (size_t)8 * ND;
    float* or0 = ob + (size_t)mglob * ND;
    float* or1 = or0 + (size_t)8 * ND;
#pragma unroll
    for (int nt = 0; nt < 8; ++nt) {
        int e = nt * 8 + 2 * c;
        float2 xv0 = *(const float2*)(xr0 + e);
        float2 w0;
        w0.x = xv0.x + o[nt][0] * li0;
        w0.y = xv0.y + o[nt][1] * li0;
        *(float2*)(or0 + e) = w0;
        float2 xv1 = *(const float2*)(xr1 + e);
        float2 w1;
        w1.x = xv1.x + o[nt][2] * li1;
        w1.y = xv1.y + o[nt][3] * li1;
        *(float2*)(or1 + e) = w1;
    }
}

// ---------------------------------------------------------------------------
// TF32 tensor-core NT GEMM, cp.async 2-stage pipeline, interleaved-k inputs.
// 128x128 tile, BK=32, 8 warps. SA=40 -> all LDS.64 frag loads conflict-free.
// mode 1: Ct[interleaved n] = tf32(relu(acc + bias))
// mode 0: Cf = acc + bias + res
// ---------------------------------------------------------------------------
#define SA 40
#define GST (128 * SA)
#define GEMM_SMEM_WORDS (4 * GST)

__global__ __launch_bounds__(256, 2) void gemm_tf32p(const uint32_t* __restrict__ A,
                                                     const uint32_t* __restrict__ Bm,
                                                     const float* __restrict__ bias,
                                                     const float* __restrict__ res,
                                                     float* __restrict__ Cf,
                                                     uint32_t* __restrict__ Ct,
                                                     int M, int N, int K, int mode)
{
    extern __shared__ uint32_t dyn[];

    const int tid  = threadIdx.x;
    const int lane = tid & 31;
    const int warp = tid >> 5;
    const int wm   = warp >> 2;
    const int wn   = warp & 3;
    const int g    = lane >> 2;
    const int c    = lane & 3;
    const int n0   = blockIdx.x * 128;
    const int m0   = blockIdx.y * 128;

    const int ldr  = tid >> 3;
    const int ldkq = (tid & 7) * 4;

    float acc[4][4][4];
#pragma unroll
    for (int mt = 0; mt < 4; ++mt)
#pragma unroll
        for (int nt = 0; nt < 4; ++nt)
#pragma unroll
            for (int r = 0; r < 4; ++r) acc[mt][nt][r] = 0.f;

    {
        uint32_t* As = dyn;
        uint32_t* Bs = dyn + GST;
#pragma unroll
        for (int it = 0; it < 4; ++it) {
            int r = ldr + it * 32;
            cp_async16(&As[r * SA + ldkq], A  + (size_t)(m0 + r) * K + ldkq);
            cp_async16(&Bs[r * SA + ldkq], Bm + (size_t)(n0 + r) * K + ldkq);
        }
    }
    CP_COMMIT();

    const int nk = K / 32;
    for (int kt = 0; kt < nk; ++kt) {
        int cur = kt & 1;
        if (kt + 1 < nk) {
            uint32_t* As = dyn + (cur ^ 1) * 2 * GST;
            uint32_t* Bs = As + GST;
            int k0 = (kt + 1) * 32;
#pragma unroll
            for (int it = 0; it < 4; ++it) {
                int r = ldr + it * 32;
                cp_async16(&As[r * SA + ldkq], A  + (size_t)(m0 + r) * K + k0 + ldkq);
                cp_async16(&Bs[r * SA + ldkq], Bm + (size_t)(n0 + r) * K + k0 + ldkq);
            }
        }
        CP_COMMIT();
        CP_WAIT1();
        __syncthreads();

        const uint32_t* As = dyn + cur * 2 * GST;
        const uint32_t* Bs = As + GST;
#pragma unroll
        for (int ks = 0; ks < 4; ++ks) {
            uint32_t af[4][4];
#pragma unroll
            for (int mt = 0; mt < 4; ++mt) {
                int m = wm * 64 + mt * 16 + g;
                uint2 um  = *(const uint2*)&As[m * SA + ks * 8 + 2 * c];
                uint2 um8 = *(const uint2*)&As[(m + 8) * SA + ks * 8 + 2 * c];
                af[mt][0] = um.x; af[mt][1] = um8.x; af[mt][2] = um.y; af[mt][3] = um8.y;
            }
            uint32_t bf[4][2];
#pragma unroll
            for (int nt = 0; nt < 4; ++nt) {
                int n = wn * 32 + nt * 8 + g;
                uint2 un = *(const uint2*)&Bs[n * SA + ks * 8 + 2 * c];
                bf[nt][0] = un.x; bf[nt][1] = un.y;
            }
#pragma unroll
            for (int mt = 0; mt < 4; ++mt)
#pragma unroll
                for (int nt = 0; nt < 4; ++nt)
                    mma_tf32(acc[mt][nt], af[mt], bf[nt]);
        }
        __syncthreads();
    }

    // Epilogue
    const int j0 = 2 * c, j1 = 2 * c + 1;
    const int p0 = 2 * (j0 & 3) + ((j0 >> 2) & 1);
    const int p1 = 2 * (j1 & 3) + ((j1 >> 2) & 1);
#pragma unroll
    for (int mt = 0; mt < 4; ++mt) {
#pragma unroll
        for (int i = 0; i < 2; ++i) {
            int m = m0 + wm * 64 + mt * 16 + g + i * 8;
#pragma unroll
            for (int nt = 0; nt < 4; ++nt) {
                int nbase = n0 + wn * 32 + nt * 8;
                float2 bv = *(const float2*)(bias + nbase + j0);
                float vx = acc[mt][nt][i * 2 + 0] + bv.x;
                float vy = acc[mt][nt][i * 2 + 1] + bv.y;
                if (mode) {
                    vx = fmaxf(vx, 0.f);
                    vy = fmaxf(vy, 0.f);
                    Ct[(size_t)m * N + nbase + p0] = f2tf32(vx);
                    Ct[(size_t)m * N + nbase + p1] = f2tf32(vy);
                } else {
                    float2 rv = *(const float2*)(res + (size_t)m * N + nbase + j0);
                    float2 v = { vx + rv.x, vy + rv.y };
                    *(float2*)(Cf + (size_t)m * N + nbase + j0) = v;
                }
            }
        }
    }
}

// ---------------------------------------------------------------------------
// LayerNorm (D=1024). Optionally writes an interleaved tf32 copy.
// ---------------------------------------------------------------------------
__global__ __launch_bounds__(256) void ln_kernel(const float* __restrict__ in,
                                                 const float* __restrict__ g,
                                                 const float* __restrict__ be,
                                                 float* __restrict__ out,
                                                 uint32_t* __restrict__ out_tf)
{
    __shared__ float sred[8], ssred[8];
    const int row = blockIdx.x;
    const int tid = threadIdx.x;
    const float4 v = *(const float4*)(in + (size_t)row * ND + tid * 4);
    float s  = v.x + v.y + v.z + v.w;
    float ss = v.x * v.x + v.y * v.y + v.z * v.z + v.w * v.w;
#pragma unroll
    for (int o = 16; o; o >>= 1) {
        s  += __shfl_xor_sync(0xffffffffu, s,  o);
        ss += __shfl_xor_sync(0xffffffffu, ss, o);
    }
    if ((tid & 31) == 0) { sred[tid >> 5] = s; ssred[tid >> 5] = ss; }
    __syncthreads();
    s = 0.f; ss = 0.f;
#pragma unroll
    for (int w = 0; w < 8; ++w) { s += sred[w]; ss += ssred[w]; }
    float mean = s * (1.f / ND);
    float var  = ss * (1.f / ND) - mean * mean;
    float rstd = rsqrtf(var + 1e-5f);
    int d = tid * 4;
    float4 gv = *(const float4*)(g + d);
    float4 bv = *(const float4*)(be + d);
    float4 ov;
    ov.x = (v.x - mean) * rstd * gv.x + bv.x;
    ov.y = (v.y - mean) * rstd * gv.y + bv.y;
    ov.z = (v.z - mean) * rstd * gv.z + bv.z;
    ov.w = (v.w - mean) * rstd * gv.w + bv.w;
    *(float4*)(out + (size_t)row * ND + d) = ov;
    if (out_tf) {
        int base = d & ~7;
        int off  = (d & 4) ? 1 : 0;
        uint32_t* p = out_tf + (size_t)row * ND + base + off;
        p[0] = f2tf32(ov.x);
        p[2] = f2tf32(ov.y);
        p[4] = f2tf32(ov.z);
        p[6] = f2tf32(ov.w);
    }
}

// ---------------------------------------------------------------------------
extern "C" void kernel_launch(void* const* d_in, const int* in_sizes, int n_in,
                              void* d_out, int out_size)
{
    (void)in_sizes; (void)n_in; (void)out_size;
    const float* x   = (const float*)d_in[0];
    const float* w1  = (const float*)d_in[1];
    const float* b1  = (const float*)d_in[2];
    const float* w2  = (const float*)d_in[3];
    const float* b2  = (const float*)d_in[4];
    const float* g1  = (const float*)d_in[5];
    const float* be1 = (const float*)d_in[6];
    const float* g2  = (const float*)d_in[7];
    const float* be2 = (const float*)d_in[8];
    float* out = (float*)d_out;

    float *attn_p, *ln1_p, *z_p;
    uint32_t *xtf_p, *xT_p, *ln1tf_p, *hidtf_p, *w1tf_p, *w2tf_p;
    cudaGetSymbolAddress((void**)&attn_p,  g_attn);
    cudaGetSymbolAddress((void**)&ln1_p,   g_ln1);
    cudaGetSymbolAddress((void**)&z_p,     g_z);
    cudaGetSymbolAddress((void**)&xtf_p,   g_xtf);
    cudaGetSymbolAddress((void**)&xT_p,    g_xT);
    cudaGetSymbolAddress((void**)&ln1tf_p, g_ln1tf);
    cudaGetSymbolAddress((void**)&hidtf_p, g_hidtf);
    cudaGetSymbolAddress((void**)&w1tf_p,  g_w1tf);
    cudaGetSymbolAddress((void**)&w2tf_p,  g_w2tf);

    const int ATT_SMEM  = ATT_SMEM_WORDS * 4;    // 110592 B
    const int GEMM_SMEM = GEMM_SMEM_WORDS * 4;   // 81920 B
    cudaFuncSetAttribute(attn_tc,    cudaFuncAttributeMaxDynamicSharedMemorySize, ATT_SMEM);
    cudaFuncSetAttribute(gemm_tf32p, cudaFuncAttributeMaxDynamicSharedMemorySize, GEMM_SMEM);

    // 0) pre-convert (interleaved) + transposed V copy
    cvt_il<<<1184, 256>>>(x,  xtf_p,  NB * NL * ND / 4);
    cvt_il<<<1184, 256>>>(w1, w1tf_p, NF * ND / 4);
    cvt_il<<<1184, 256>>>(w2, w2tf_p, ND * NF / 4);
    transpose_xT<<<dim3(NB * NH, NL / 128), 256>>>(x, xT_p);
    // 1) attention + residual
    attn_tc<<<dim3(NB * NH, NL / 128), 256, ATT_SMEM>>>(xtf_p, xT_p, x, attn_p);
    // 2) LN1 (f32 + interleaved tf32)
    ln_kernel<<<NB * NL, 256>>>(attn_p, g1, be1, ln1_p, ln1tf_p);
    // 3) hidden = tf32(relu(ln1 @ w1^T + b1))   M=8192 N=4096 K=1024
    gemm_tf32p<<<dim3(NF / 128, (NB * NL) / 128), 256, GEMM_SMEM>>>(
        ln1tf_p, w1tf_p, b1, nullptr, nullptr, hidtf_p, NB * NL, NF, ND, 1);
    // 4) z = hidden @ w2^T + b2 + ln1           M=8192 N=1024 K=4096
    gemm_tf32p<<<dim3(ND / 128, (NB * NL) / 128), 256, GEMM_SMEM>>>(
        hidtf_p, w2tf_p, b2, ln1_p, z_p, nullptr, NB * NL, ND, NF, 0);
    // 5) LN2 -> output
    ln_kernel<<<NB * NL, 256>>>(z_p, g2, be2, out, nullptr);
}